// round 2
// baseline (speedup 1.0000x reference)
#include <cuda_runtime.h>

#define NCH   80      // C0 + 3*C1 = 32 + 48
#define FDIM  664     // 528 + 136
#define NMAX  300000

__constant__ float cW[FDIM];
__device__ float g_ex[NMAX];

__device__ __forceinline__ float ex2f(float x) {
    float r;
    asm("ex2.approx.ftz.f32 %0, %1;" : "=f"(r) : "f"(x));
    return r;
}

__global__ __launch_bounds__(256) void gap_kernel(
    const float* __restrict__ node_ft,
    const int*   __restrict__ bidx,
    float*       __restrict__ out,
    int N)
{
    // Constants (selu lambda/alpha, all folded into log2-space)
    const float SQL    = 1.2011224087864498f;   // sqrt(log2(e))
    const float LLN2   = (float)(1.0507009873554805 * 0.6931471805599453); // lambda*ln2
    const float LA     = 1.7580993408473766f;   // lambda*alpha
    const float LOG2E  = 1.4426950408889634f;

    __shared__ int   s_lo, s_hi;
    __shared__ float s_warp[8];
    __shared__ float s_inv;
    __shared__ float s_red[3][NCH];

    const int g   = blockIdx.x;
    const int tid = threadIdx.x;

    if (tid == 0) {
        // binary search: [lo, hi) = range of nodes with batch_index == g
        int lo = 0, hi = N;
        while (lo < hi) { int m = (lo + hi) >> 1; if (bidx[m] < g) lo = m + 1; else hi = m; }
        s_lo = lo;
        int lo2 = lo, hi2 = N;
        while (lo2 < hi2) { int m = (lo2 + hi2) >> 1; if (bidx[m] < g + 1) lo2 = m + 1; else hi2 = m; }
        s_hi = lo2;
    }
    __syncthreads();
    const int lo = s_lo, hi = s_hi;

    // per-component v scale: sqrt(log2(e)/sqrt(3))  (constant-folded)
    const float VSC = sqrtf(1.4426950408889634f / 1.7320508075688772f);

    // ---------------- Phase 1: logits -> exp, per-node ----------------
    float zpart = 0.f;
    for (int n = lo + tid; n < hi; n += blockDim.x) {
        const float4* row = reinterpret_cast<const float4*>(node_ft + (size_t)n * NCH);
        float ss[32], vv[48];
        #pragma unroll
        for (int k = 0; k < 8; k++) {
            float4 q = row[k];
            ss[4*k+0] = q.x * SQL; ss[4*k+1] = q.y * SQL;
            ss[4*k+2] = q.z * SQL; ss[4*k+3] = q.w * SQL;
        }
        #pragma unroll
        for (int k = 0; k < 12; k++) {
            float4 q = row[8 + k];
            vv[4*k+0] = q.x * VSC; vv[4*k+1] = q.y * VSC;
            vv[4*k+2] = q.z * VSC; vv[4*k+3] = q.w * VSC;
        }

        float acc = 0.f;
        int f = 0;
        // s-part: 528 upper-triangular pair products
        #pragma unroll
        for (int i = 0; i < 32; i++) {
            #pragma unroll
            for (int j = i; j < 32; j++) {
                float p2 = ss[i] * ss[j];            // = s_i*s_j * log2(e)
                float e  = ex2f(p2);                  // = exp(s_i*s_j)
                float r  = p2 > 0.f ? LLN2 * p2       // lambda * x
                                    : fmaf(e, LA, -LA); // lambda*alpha*(exp(x)-1)
                acc = fmaf(cW[f], r, acc);
                f++;
            }
        }
        // v-part: 136 upper-triangular 3-dim dots (pre-scaled by sqrt(log2e/sqrt3))
        #pragma unroll
        for (int i = 0; i < 16; i++) {
            #pragma unroll
            for (int j = i; j < 16; j++) {
                float p2 = vv[3*i] * vv[3*j];
                p2 = fmaf(vv[3*i+1], vv[3*j+1], p2);
                p2 = fmaf(vv[3*i+2], vv[3*j+2], p2);
                float e  = ex2f(p2);
                float r  = p2 > 0.f ? LLN2 * p2 : fmaf(e, LA, -LA);
                acc = fmaf(cW[f], r, acc);
                f++;
            }
        }

        float ex = ex2f(acc * LOG2E);   // exp(logit)
        g_ex[n] = ex;
        zpart  += ex;
    }

    // ---------------- block reduce z ----------------
    #pragma unroll
    for (int o = 16; o > 0; o >>= 1) zpart += __shfl_down_sync(0xffffffffu, zpart, o);
    if ((tid & 31) == 0) s_warp[tid >> 5] = zpart;
    __syncthreads();
    if (tid == 0) {
        float z = 0.f;
        #pragma unroll
        for (int w = 0; w < 8; w++) z += s_warp[w];
        s_inv = (hi > lo) ? 1.f / z : 0.f;
    }
    __syncthreads();
    const float inv = s_inv;

    // ---------------- Phase 2: weighted segment sum ----------------
    float acc = 0.f;
    const int grp = tid / NCH;         // 0..2 active for tid < 240
    const int ch  = tid - grp * NCH;
    if (tid < 3 * NCH) {
        for (int n = lo + grp; n < hi; n += 3)
            acc = fmaf(node_ft[(size_t)n * NCH + ch], g_ex[n], acc);
        s_red[grp][ch] = acc;
    }
    __syncthreads();
    if (tid < NCH) {
        out[(size_t)g * NCH + tid] =
            (s_red[0][tid] + s_red[1][tid] + s_red[2][tid]) * inv;
    }
}

extern "C" void kernel_launch(void* const* d_in, const int* in_sizes, int n_in,
                              void* d_out, int out_size)
{
    const float* node_ft = nullptr;
    const int*   bidx    = nullptr;
    const float* W       = nullptr;
    int N = 0;
    // identify inputs by element count (robust to scalar num_graphs being present)
    for (int i = 0; i < n_in; i++) {
        int s = in_sizes[i];
        if (s >= 1000000)       { node_ft = (const float*)d_in[i]; N = s / NCH; }
        else if (s == FDIM)     { W = (const float*)d_in[i]; }
        else if (s >= 100000)   { bidx = (const int*)d_in[i]; }
    }
    const int NG = out_size / NCH;

    cudaMemcpyToSymbolAsync(cW, W, FDIM * sizeof(float), 0,
                            cudaMemcpyDeviceToDevice, 0);
    gap_kernel<<<NG, 256>>>(node_ft, bidx, (float*)d_out, N);
}

// round 6
// speedup vs baseline: 1.1338x; 1.1338x over previous
#include <cuda_runtime.h>

#define NCH   80      // C0 + 3*C1 = 32 + 48
#define FDIM  664     // 528 + 136
#define NMAX  300000

__device__ float g_ex[NMAX];

__device__ __forceinline__ float ex2f(float x) {
    float r;
    asm("ex2.approx.ftz.f32 %0, %1;" : "=f"(r) : "f"(x));
    return r;
}

// ---------------------------------------------------------------------------
// Kernel 1: node-parallel logit + exp. One thread = one node. Perfect balance.
//
// selu(x) = lam*max(x,0) + lam*alpha*(min(exp(x),1) - 1)
// The constant  -lam*alpha*sum(W)  is identical for every node and cancels in
// the softmax, so it is dropped. Working in log2 space throughout.
// ---------------------------------------------------------------------------
__global__ __launch_bounds__(256) void gap_k1(
    const float* __restrict__ node_ft,
    const float* __restrict__ W,
    int N)
{
    __shared__ float2 w12[FDIM];

    const float LAM    = 1.0507009873554805f;                       // lambda
    const float LAL2E  = 1.7580993408473766f * 1.4426950408889634f; // lam*alpha*log2e

    for (int f = threadIdx.x; f < FDIM; f += 256) {
        float w = W[f];
        w12[f] = make_float2(w * LAM, w * LAL2E);
    }
    __syncthreads();

    const int n = blockIdx.x * 256 + threadIdx.x;
    if (n >= N) return;

    const float SQL = 1.2011224087864498f;                               // sqrt(log2 e)
    const float VSC = sqrtf(1.4426950408889634f / 1.7320508075688772f);  // sqrt(log2e/sqrt3)

    const float4* row = reinterpret_cast<const float4*>(node_ft + (size_t)n * NCH);

    float a1 = 0.f, a2 = 0.f, b1 = 0.f, b2 = 0.f;

    // ---- s-part: 32 scalars, 528 upper-triangular pairs ----
    {
        float ss[32];
        #pragma unroll
        for (int k = 0; k < 8; k++) {
            float4 q = row[k];
            ss[4*k+0] = q.x * SQL; ss[4*k+1] = q.y * SQL;
            ss[4*k+2] = q.z * SQL; ss[4*k+3] = q.w * SQL;
        }
        int f = 0;
        #pragma unroll
        for (int i = 0; i < 32; i++) {
            #pragma unroll
            for (int j = i; j < 32; j++) {
                float p2 = ss[i] * ss[j];           // x * log2e
                float e  = ex2f(p2);                // exp(x)
                float2 w = w12[f];
                float mp = fmaxf(p2, 0.f);
                float me = fminf(e, 1.f);
                if (((i ^ j) & 1) == 0) {
                    a1 = fmaf(w.x, mp, a1);
                    a2 = fmaf(w.y, me, a2);
                } else {
                    b1 = fmaf(w.x, mp, b1);
                    b2 = fmaf(w.y, me, b2);
                }
                f++;
            }
        }
    }

    // ---- v-part: 16 vectors of dim 3, 136 upper-triangular dot pairs ----
    {
        float vv[48];
        #pragma unroll
        for (int k = 0; k < 12; k++) {
            float4 q = row[8 + k];
            vv[4*k+0] = q.x * VSC; vv[4*k+1] = q.y * VSC;
            vv[4*k+2] = q.z * VSC; vv[4*k+3] = q.w * VSC;
        }
        int f = 528;
        #pragma unroll
        for (int i = 0; i < 16; i++) {
            #pragma unroll
            for (int j = i; j < 16; j++) {
                float p2 = vv[3*i] * vv[3*j];
                p2 = fmaf(vv[3*i+1], vv[3*j+1], p2);
                p2 = fmaf(vv[3*i+2], vv[3*j+2], p2);
                float e  = ex2f(p2);
                float2 w = w12[f];
                float mp = fmaxf(p2, 0.f);
                float me = fminf(e, 1.f);
                if (((i ^ j) & 1) == 0) {
                    a1 = fmaf(w.x, mp, a1);
                    a2 = fmaf(w.y, me, a2);
                } else {
                    b1 = fmaf(w.x, mp, b1);
                    b2 = fmaf(w.y, me, b2);
                }
                f++;
            }
        }
    }

    g_ex[n] = ex2f((a1 + b1) + (a2 + b2));
}

// ---------------------------------------------------------------------------
// Kernel 2: per-graph softmax-normalized segment sum.
// Block = graph. node_ft re-read is L2-resident (96MB < 126MB L2).
// ---------------------------------------------------------------------------
__global__ __launch_bounds__(256) void gap_k2(
    const float* __restrict__ node_ft,
    const int*   __restrict__ bidx,
    float*       __restrict__ out,
    int N)
{
    __shared__ int    s_lo, s_hi;
    __shared__ float  s_warp[8];
    __shared__ float  s_inv;
    __shared__ float4 s_red4[12 * 20];  // 12 node-groups x 20 float4 = 80 ch (16B aligned!)

    const int g   = blockIdx.x;
    const int tid = threadIdx.x;

    if (tid == 0) {
        int lo = 0, hi = N;
        while (lo < hi) { int m = (lo + hi) >> 1; if (bidx[m] < g) lo = m + 1; else hi = m; }
        s_lo = lo;
        int lo2 = lo, hi2 = N;
        while (lo2 < hi2) { int m = (lo2 + hi2) >> 1; if (bidx[m] < g + 1) lo2 = m + 1; else hi2 = m; }
        s_hi = lo2;
    }
    __syncthreads();
    const int lo = s_lo, hi = s_hi;

    // ---- z = sum of ex over this graph's nodes ----
    float z = 0.f;
    for (int n = lo + tid; n < hi; n += 256) z += g_ex[n];
    #pragma unroll
    for (int o = 16; o > 0; o >>= 1) z += __shfl_down_sync(0xffffffffu, z, o);
    if ((tid & 31) == 0) s_warp[tid >> 5] = z;
    __syncthreads();
    if (tid == 0) {
        float t = 0.f;
        #pragma unroll
        for (int w = 0; w < 8; w++) t += s_warp[w];
        s_inv = (hi > lo) ? 1.f / t : 0.f;
    }
    __syncthreads();
    const float inv = s_inv;

    // ---- weighted segment sum: 12 groups x 20 float4-lanes ----
    if (tid < 240) {
        const int grp = tid / 20;
        const int c4  = tid - grp * 20;
        float4 acc = make_float4(0.f, 0.f, 0.f, 0.f);
        const float4* nf4 = reinterpret_cast<const float4*>(node_ft);
        for (int n = lo + grp; n < hi; n += 12) {
            float  w = g_ex[n];
            float4 q = nf4[(size_t)n * 20 + c4];
            acc.x = fmaf(q.x, w, acc.x);
            acc.y = fmaf(q.y, w, acc.y);
            acc.z = fmaf(q.z, w, acc.z);
            acc.w = fmaf(q.w, w, acc.w);
        }
        s_red4[tid] = acc;   // floats at grp*80 + c4*4 + k
    }
    __syncthreads();

    if (tid < NCH) {
        const float* s_red = reinterpret_cast<const float*>(s_red4);
        float s = 0.f;
        #pragma unroll
        for (int q = 0; q < 12; q++) s += s_red[q * NCH + tid];
        out[(size_t)g * NCH + tid] = s * inv;
    }
}

extern "C" void kernel_launch(void* const* d_in, const int* in_sizes, int n_in,
                              void* d_out, int out_size)
{
    const float* node_ft = nullptr;
    const int*   bidx    = nullptr;
    const float* W       = nullptr;
    int N = 0;
    for (int i = 0; i < n_in; i++) {
        int s = in_sizes[i];
        if (s >= 1000000)       { node_ft = (const float*)d_in[i]; N = s / NCH; }
        else if (s == FDIM)     { W = (const float*)d_in[i]; }
        else if (s >= 100000)   { bidx = (const int*)d_in[i]; }
    }
    const int NG = out_size / NCH;

    gap_k1<<<(N + 255) / 256, 256>>>(node_ft, W, N);
    gap_k2<<<NG, 256>>>(node_ft, bidx, (float*)d_out, N);
}

// round 14
// speedup vs baseline: 1.3902x; 1.2261x over previous
#include <cuda_runtime.h>

#define NCH   80      // C0 + 3*C1 = 32 + 48
#define FDIM  664     // 528 + 136
#define NGMAX 1024

__device__ float g_z[NGMAX];          // per-graph sum of exp(logit)
__device__ float g_A[NGMAX * NCH];    // per-graph sum of ft*exp(logit)

__device__ __forceinline__ float ex2f(float x) {
    float r;
    asm("ex2.approx.ftz.f32 %0, %1;" : "=f"(r) : "f"(x));
    return r;
}

// ---------------------------------------------------------------------------
// Fused kernel.
// Phase 1: one thread = one node; compute exp(logit) (MUFU-floor bound).
// Phase 2: same block re-reads its 256 node rows (L1/L2-hot, 80KB) as
//          12 groups x 20 float4-lanes, weights by s_ex, and accumulates
//          per-graph runs; sorted batch_index -> <=2-3 boundary flushes per
//          walk, each flush = 4 RED.ADD.F32. Threads 240..255 accumulate z.
//
// selu(x) = lam*max(x,0) + lam*alpha*(min(exp(x),1) - 1); the node-invariant
// constant -lam*alpha*sum(W) cancels in the softmax and is dropped.
// Log2 space throughout phase 1 (ss pre-scaled by sqrt(log2e), vv by
// sqrt(log2e/sqrt3)); phase 2 uses RAW node_ft, so no un-scaling needed.
// ---------------------------------------------------------------------------
__global__ __launch_bounds__(256) void gap_k1(
    const float* __restrict__ node_ft,
    const float* __restrict__ W,
    const int*   __restrict__ bidx,
    int N)
{
    __shared__ float2 w12[FDIM];
    __shared__ float  s_ex[256];
    __shared__ int    s_g[256];

    const float LAM    = 1.0507009873554805f;                       // lambda
    const float LAL2E  = 1.7580993408473766f * 1.4426950408889634f; // lam*alpha*log2e

    for (int f = threadIdx.x; f < FDIM; f += 256) {
        float w = W[f];
        w12[f] = make_float2(w * LAM, w * LAL2E);
    }

    const int tid  = threadIdx.x;
    const int base = blockIdx.x * 256;
    const int nLoc = min(256, N - base);   // nodes this block owns
    const int n    = base + tid;
    const bool ok  = (tid < nLoc);
    const int  nn  = ok ? n : (N - 1);

    const float SQL = 1.2011224087864498f;                               // sqrt(log2 e)
    const float VSC = sqrtf(1.4426950408889634f / 1.7320508075688772f);  // sqrt(log2e/sqrt3)

    const float4* row = reinterpret_cast<const float4*>(node_ft + (size_t)nn * NCH);

    float a1 = 0.f, a2 = 0.f, b1 = 0.f, b2 = 0.f;

    // ---- s-part: 32 scalars, 528 upper-triangular pairs ----
    {
        float ss[32];
        #pragma unroll
        for (int k = 0; k < 8; k++) {
            float4 q = row[k];
            ss[4*k+0] = q.x * SQL; ss[4*k+1] = q.y * SQL;
            ss[4*k+2] = q.z * SQL; ss[4*k+3] = q.w * SQL;
        }
        __syncthreads();   // w12 ready (placed after loads to overlap)
        int f = 0;
        #pragma unroll
        for (int i = 0; i < 32; i++) {
            #pragma unroll
            for (int j = i; j < 32; j++) {
                float p2 = ss[i] * ss[j];           // x * log2e
                float e  = ex2f(p2);                // exp(x)
                float2 w = w12[f];
                float mp = fmaxf(p2, 0.f);
                float me = fminf(e, 1.f);
                if (((i ^ j) & 1) == 0) { a1 = fmaf(w.x, mp, a1); a2 = fmaf(w.y, me, a2); }
                else                    { b1 = fmaf(w.x, mp, b1); b2 = fmaf(w.y, me, b2); }
                f++;
            }
        }
    }
    // ---- v-part: 16 vectors of dim 3, 136 upper-triangular dots ----
    {
        float vv[48];
        #pragma unroll
        for (int k = 0; k < 12; k++) {
            float4 q = row[8 + k];
            vv[4*k+0] = q.x * VSC; vv[4*k+1] = q.y * VSC;
            vv[4*k+2] = q.z * VSC; vv[4*k+3] = q.w * VSC;
        }
        int f = 528;
        #pragma unroll
        for (int i = 0; i < 16; i++) {
            #pragma unroll
            for (int j = i; j < 16; j++) {
                float p2 = vv[3*i] * vv[3*j];
                p2 = fmaf(vv[3*i+1], vv[3*j+1], p2);
                p2 = fmaf(vv[3*i+2], vv[3*j+2], p2);
                float e  = ex2f(p2);
                float2 w = w12[f];
                float mp = fmaxf(p2, 0.f);
                float me = fminf(e, 1.f);
                if (((i ^ j) & 1) == 0) { a1 = fmaf(w.x, mp, a1); a2 = fmaf(w.y, me, a2); }
                else                    { b1 = fmaf(w.x, mp, b1); b2 = fmaf(w.y, me, b2); }
                f++;
            }
        }
    }

    s_ex[tid] = ok ? ex2f((a1 + b1) + (a2 + b2)) : 0.f;
    s_g[tid]  = ok ? bidx[nn] : -1;
    __syncthreads();

    // ---- Phase 2: weighted per-graph accumulation (L1-hot re-read) ----
    if (tid < 240) {
        const int grp = tid / 20;          // 12 groups
        const int c4  = tid - grp * 20;    // float4 lane within row
        const float4* nf4 = reinterpret_cast<const float4*>(node_ft);

        int    cur_g = -1;
        float4 acc   = make_float4(0.f, 0.f, 0.f, 0.f);
        for (int i = grp; i < nLoc; i += 12) {
            int   g = s_g[i];
            float w = s_ex[i];
            if (g != cur_g) {
                if (cur_g >= 0) {
                    float* dst = &g_A[(size_t)cur_g * NCH + c4 * 4];
                    atomicAdd(dst + 0, acc.x);
                    atomicAdd(dst + 1, acc.y);
                    atomicAdd(dst + 2, acc.z);
                    atomicAdd(dst + 3, acc.w);
                }
                cur_g = g;
                acc = make_float4(0.f, 0.f, 0.f, 0.f);
            }
            float4 q = nf4[(size_t)(base + i) * 20 + c4];
            acc.x = fmaf(q.x, w, acc.x);
            acc.y = fmaf(q.y, w, acc.y);
            acc.z = fmaf(q.z, w, acc.z);
            acc.w = fmaf(q.w, w, acc.w);
        }
        if (cur_g >= 0) {
            float* dst = &g_A[(size_t)cur_g * NCH + c4 * 4];
            atomicAdd(dst + 0, acc.x);
            atomicAdd(dst + 1, acc.y);
            atomicAdd(dst + 2, acc.z);
            atomicAdd(dst + 3, acc.w);
        }
    } else {
        // ---- z accumulation: 16 threads walk all 256 local nodes ----
        const int lane0 = tid - 240;       // 0..15
        int   cur_g = -1;
        float acc   = 0.f;
        for (int i = lane0; i < nLoc; i += 16) {
            int g = s_g[i];
            if (g != cur_g) {
                if (cur_g >= 0) atomicAdd(&g_z[cur_g], acc);
                cur_g = g;
                acc = 0.f;
            }
            acc += s_ex[i];
        }
        if (cur_g >= 0) atomicAdd(&g_z[cur_g], acc);
    }
}

// ---------------------------------------------------------------------------
// Divide kernel: out = A / z
// ---------------------------------------------------------------------------
__global__ __launch_bounds__(256) void gap_div(float* __restrict__ out, int total)
{
    int i = blockIdx.x * 256 + threadIdx.x;
    if (i >= total) return;
    float z = g_z[i / NCH];
    out[i] = (z > 0.f) ? g_A[i] / z : 0.f;
}

extern "C" void kernel_launch(void* const* d_in, const int* in_sizes, int n_in,
                              void* d_out, int out_size)
{
    const float* node_ft = nullptr;
    const int*   bidx    = nullptr;
    const float* W       = nullptr;
    int N = 0;
    for (int i = 0; i < n_in; i++) {
        int s = in_sizes[i];
        if (s >= 1000000)       { node_ft = (const float*)d_in[i]; N = s / NCH; }
        else if (s == FDIM)     { W = (const float*)d_in[i]; }
        else if (s >= 100000)   { bidx = (const int*)d_in[i]; }
    }

    void *pz = nullptr, *pA = nullptr;
    cudaGetSymbolAddress(&pz, g_z);
    cudaGetSymbolAddress(&pA, g_A);
    cudaMemsetAsync(pz, 0, NGMAX * sizeof(float), 0);
    cudaMemsetAsync(pA, 0, (size_t)NGMAX * NCH * sizeof(float), 0);

    gap_k1<<<(N + 255) / 256, 256>>>(node_ft, W, bidx, N);
    gap_div<<<(out_size + 255) / 256, 256>>>((float*)d_out, out_size);
}